// round 1
// baseline (speedup 1.0000x reference)
#include <cuda_runtime.h>
#include <math.h>

#define BB 512
#define ZI 16
#define TT 8
#define DD 128
#define MROWS (BB*ZI)   /* 8192 img rows  */
#define NCOLS (BB*TT)   /* 4096 text rows */

#define MT 64
#define NT 64
#define SS 68           /* d-major smem row stride (floats), 16B aligned */

// Scratch (static __device__ arrays: allocation-free per harness rules)
__device__ float g_imgn [(size_t)MROWS * DD];        // 4 MB
__device__ float g_textn[(size_t)NCOLS * DD];        // 2 MB
__device__ float g_covar[(size_t)BB * NCOLS];        // 8 MB
__device__ float g_partial[BB];                      // 1.125*diag - log den_i2t
__device__ float g_dent2i[NCOLS];

// ---------------------------------------------------------------------------
// 1) L2 normalize rows of img and text. One warp per row of 128 floats.
// ---------------------------------------------------------------------------
__global__ void knorm(const float* __restrict__ img, const float* __restrict__ text) {
    int wid  = blockIdx.x * 8 + (threadIdx.x >> 5);
    int lane = threadIdx.x & 31;
    const float* src;
    float* dst;
    if (wid < MROWS) {
        src = img   + (size_t)wid * DD;
        dst = g_imgn + (size_t)wid * DD;
    } else {
        int r = wid - MROWS;
        src = text    + (size_t)r * DD;
        dst = g_textn + (size_t)r * DD;
    }
    float4 v = ((const float4*)src)[lane];           // 32 lanes * 4 = 128
    float s = v.x*v.x + v.y*v.y + v.z*v.z + v.w*v.w;
    #pragma unroll
    for (int o = 16; o; o >>= 1) s += __shfl_xor_sync(0xffffffffu, s, o);
    float inv = 1.0f / fmaxf(sqrtf(s), 1e-12f);      // matches F.normalize eps
    v.x *= inv; v.y *= inv; v.z *= inv; v.w *= inv;
    ((float4*)dst)[lane] = v;
}

// ---------------------------------------------------------------------------
// 2) Fused GEMM + max-over-i.
//    Block tile: 64 M-rows (4 b-groups of 16) x 64 N-cols, K=128 fully resident.
//    128 threads, 8x4 micro-tile each. Warp w owns b-group w (rows 16w..16w+15),
//    so the max over i finishes with a single shfl_xor(16).
// ---------------------------------------------------------------------------
__global__ void __launch_bounds__(128) kgemm() {
    extern __shared__ float sh[];
    float* sI = sh;             // [DD][SS] d-major img tile
    float* sT = sh + DD * SS;   // [DD][SS] d-major text tile

    const int tid = threadIdx.x;
    const int m0  = blockIdx.y * MT;
    const int n0  = blockIdx.x * NT;

    const float* gI = g_imgn  + (size_t)m0 * DD;
    const float* gT = g_textn + (size_t)n0 * DD;

    // Coalesced global read (idx = r*128 + d), transposed smem write.
    // Lanes write consecutive d -> stride SS words -> banks step by 4, 8-way
    // spread; load phase is tiny vs. the FFMA mainloop.
    #pragma unroll 4
    for (int idx = tid; idx < MT * DD; idx += 128) {
        int r = idx >> 7, d = idx & 127;
        sI[d * SS + r] = gI[idx];
        sT[d * SS + r] = gT[idx];
    }
    __syncthreads();

    const int tx = tid & 15;        // 16 column-groups of 4
    const int ty = tid >> 4;        // 8 row-groups of 8
    const float* pI = sI + ty * 8;
    const float* pT = sT + tx * 4;

    float acc[8][4];
    #pragma unroll
    for (int i = 0; i < 8; i++)
        #pragma unroll
        for (int j = 0; j < 4; j++) acc[i][j] = 0.0f;

    #pragma unroll 4
    for (int d = 0; d < DD; d++) {
        float4 bv = *(const float4*)(pT + d * SS);
        float4 a0 = *(const float4*)(pI + d * SS);
        float4 a1 = *(const float4*)(pI + d * SS + 4);
        float av[8] = {a0.x, a0.y, a0.z, a0.w, a1.x, a1.y, a1.z, a1.w};
        float bb[4] = {bv.x, bv.y, bv.z, bv.w};
        #pragma unroll
        for (int i = 0; i < 8; i++)
            #pragma unroll
            for (int j = 0; j < 4; j++)
                acc[i][j] += av[i] * bb[j];
    }

    // Max over this thread's 8 rows, then over the partner half-warp
    // (lane ^ 16 holds the other 8 rows of the same 16-row b-group).
    float cm[4];
    #pragma unroll
    for (int j = 0; j < 4; j++) {
        float m = acc[0][j];
        #pragma unroll
        for (int i = 1; i < 8; i++) m = fmaxf(m, acc[i][j]);
        m = fmaxf(m, __shfl_xor_sync(0xffffffffu, m, 16));
        cm[j] = m;
    }

    if ((ty & 1) == 0) {                        // lanes 0..15 of each warp
        int b   = (m0 >> 4) + (ty >> 1);        // global b index
        int col = n0 + tx * 4;
        *(float4*)(g_covar + (size_t)b * NCOLS + col) =
            make_float4(cm[0], cm[1], cm[2], cm[3]);
    }
}

// ---------------------------------------------------------------------------
// 3a) Per-b: den_i2t[b] = sum_{c,t} exp(covar), plus diag term.
// ---------------------------------------------------------------------------
__global__ void kred_i2t() {
    const int b = blockIdx.x, tid = threadIdx.x;
    const float* row = g_covar + (size_t)b * NCOLS;
    float s = 0.0f;
    for (int j = tid; j < NCOLS; j += 256) s += expf(row[j]);
    __shared__ float sm[256];
    sm[tid] = s; __syncthreads();
    for (int o = 128; o; o >>= 1) {
        if (tid < o) sm[tid] += sm[tid + o];
        __syncthreads();
    }
    if (tid == 0) {
        float diag = 0.0f;
        #pragma unroll
        for (int t = 0; t < TT; t++) diag += row[b * TT + t];
        g_partial[b] = 1.125f * diag - logf(sm[0]);   // (1 + 1/T) = 1.125
    }
}

// ---------------------------------------------------------------------------
// 3b) Per-column: den_t2i[ct] = sum_b exp(covar[b][ct]). Coalesced over ct.
// ---------------------------------------------------------------------------
__global__ void kred_t2i() {
    const int col = blockIdx.x * 256 + threadIdx.x;
    float s = 0.0f;
    for (int b = 0; b < BB; b++)
        s += expf(g_covar[(size_t)b * NCOLS + col]);
    g_dent2i[col] = s;
}

// ---------------------------------------------------------------------------
// 4) Final scalar: loss = -sum_b [ partial[b] - sum_t log den_t2i[b*T+t] ]
// ---------------------------------------------------------------------------
__global__ void kfinal(float* __restrict__ out) {
    const int b = threadIdx.x;                  // 512 threads
    float v = g_partial[b];
    #pragma unroll
    for (int t = 0; t < TT; t++) v -= logf(g_dent2i[b * TT + t]);
    __shared__ float sm[512];
    sm[b] = v; __syncthreads();
    for (int o = 256; o; o >>= 1) {
        if (b < o) sm[b] += sm[b + o];
        __syncthreads();
    }
    if (b == 0) out[0] = -sm[0];
}

// ---------------------------------------------------------------------------
extern "C" void kernel_launch(void* const* d_in, const int* in_sizes, int n_in,
                              void* d_out, int out_size) {
    const float* img  = (const float*)d_in[0];
    const float* text = (const float*)d_in[1];
    // Defensive: identify tensors by element count in case of ordering surprises.
    if (n_in >= 2 && in_sizes[0] == NCOLS * DD && in_sizes[1] == MROWS * DD) {
        const float* t = img; img = text; text = t;
    }

    const int smem = 2 * DD * SS * (int)sizeof(float);   // 69632 B
    cudaFuncSetAttribute(kgemm, cudaFuncAttributeMaxDynamicSharedMemorySize, smem);

    knorm<<<(MROWS + NCOLS) / 8, 256>>>(img, text);
    kgemm<<<dim3(NCOLS / NT, MROWS / MT), 128, smem>>>();
    kred_i2t<<<BB, 256>>>();
    kred_t2i<<<NCOLS / 256, 256>>>();
    kfinal<<<1, 512>>>((float*)d_out);
}

// round 3
// speedup vs baseline: 4.7480x; 4.7480x over previous
#include <cuda_runtime.h>
#include <cuda_bf16.h>
#include <math.h>
#include <cstdint>

#define BB 512
#define ZI 16
#define TT 8
#define DD 128
#define MROWS (BB*ZI)   /* 8192 */
#define NCOLS (BB*TT)   /* 4096 */

// ---------------- scratch (static __device__, allocation-free) -------------
__device__ __nv_bfloat162 g_imgh [(size_t)MROWS * (DD/2)];   // 2 MB
__device__ __nv_bfloat162 g_texth[(size_t)NCOLS * (DD/2)];   // 1 MB
__device__ float g_expc[(size_t)BB * NCOLS];                 // 8 MB exp(covar)
__device__ float g_diag[NCOLS];                              // raw covar diag
__device__ float g_partial[BB];
__device__ float g_t2ipart[8 * NCOLS];

__device__ __forceinline__ uint32_t smem_u32(const void* p) {
    uint32_t a;
    asm("{ .reg .u64 t; cvta.to.shared.u64 t, %1; cvt.u32.u64 %0, t; }"
        : "=r"(a) : "l"(p));
    return a;
}

#define LDSM4(r0,r1,r2,r3,addr) \
    asm volatile("ldmatrix.sync.aligned.m8n8.x4.shared.b16 {%0,%1,%2,%3}, [%4];" \
                 : "=r"(r0),"=r"(r1),"=r"(r2),"=r"(r3) : "r"(addr))

#define MMA16816(c,a0,a1,a2,a3,b0,b1) \
    asm volatile("mma.sync.aligned.m16n8k16.row.col.f32.bf16.bf16.f32 " \
                 "{%0,%1,%2,%3},{%4,%5,%6,%7},{%8,%9},{%0,%1,%2,%3};" \
                 : "+f"(c[0]),"+f"(c[1]),"+f"(c[2]),"+f"(c[3]) \
                 : "r"(a0),"r"(a1),"r"(a2),"r"(a3),"r"(b0),"r"(b1))

// ---------------------------------------------------------------------------
// 1) L2 normalize + convert to packed bf16. One warp per row of 128 floats.
// ---------------------------------------------------------------------------
__global__ void knorm(const float* __restrict__ img, const float* __restrict__ text) {
    int wid  = blockIdx.x * 8 + (threadIdx.x >> 5);
    int lane = threadIdx.x & 31;
    const float* src; __nv_bfloat162* dst;
    if (wid < MROWS) { src = img + (size_t)wid * DD;  dst = g_imgh + (size_t)wid * (DD/2); }
    else { int r = wid - MROWS; src = text + (size_t)r * DD; dst = g_texth + (size_t)r * (DD/2); }
    float4 v = ((const float4*)src)[lane];
    float s = v.x*v.x + v.y*v.y + v.z*v.z + v.w*v.w;
    #pragma unroll
    for (int o = 16; o; o >>= 1) s += __shfl_xor_sync(0xffffffffu, s, o);
    float inv = 1.0f / fmaxf(sqrtf(s), 1e-12f);
    dst[lane*2]   = __floats2bfloat162_rn(v.x*inv, v.y*inv);
    dst[lane*2+1] = __floats2bfloat162_rn(v.z*inv, v.w*inv);
}

// ---------------------------------------------------------------------------
// 2) HMMA bf16 GEMM + max-over-i + exp.  CTA tile 128x128x128, 256 threads.
//    Warp w owns m-rows [16w,16w+16) = one b-group, all 128 n-cols.
//    SMEM rows padded to 272B: 272 mod 128 = 16 -> the 8 row-chunks of an
//    ldmatrix land on distinct 16B positions mod 128B -> conflict-free.
// ---------------------------------------------------------------------------
#define RPITCH 272
#define SM_BYTES (2 * 128 * RPITCH)     /* 69632 */

__global__ void __launch_bounds__(256) kgemm() {
    extern __shared__ char sh[];
    char* shA = sh;
    char* shB = sh + 128 * RPITCH;

    const int tid  = threadIdx.x;
    const int lane = tid & 31, w = tid >> 5;
    const int m0 = blockIdx.y * 128, n0 = blockIdx.x * 128;

    // ---- load tiles (each row: 128 bf16 = 16 uint4), pad rows to 272B -----
    const uint4* gA = (const uint4*)(g_imgh  + (size_t)m0 * (DD/2));
    const uint4* gB = (const uint4*)(g_texth + (size_t)n0 * (DD/2));
    #pragma unroll
    for (int it = tid; it < 2048; it += 256) {
        int row = it >> 4, q = it & 15;
        *(uint4*)(shA + row * RPITCH + q * 16) = gA[it];
        *(uint4*)(shB + row * RPITCH + q * 16) = gB[it];
    }
    __syncthreads();

    const uint32_t sA = smem_u32(shA), sB = smem_u32(shB);
    // A: lanes 0-15 -> rows m 0..15 (k lo), lanes 16-31 same rows k hi chunk
    const uint32_t aBase = sA + (uint32_t)(w * 16 + (lane & 15)) * RPITCH
                              + (uint32_t)(lane >> 4) * 16;
    // B: lanes 0-7 rows n0..7 klo | 8-15 same rows khi | 16-23 n8..15 klo | 24-31 khi
    const uint32_t bBase = sB + (uint32_t)((lane & 7) + ((lane >> 4) << 3)) * RPITCH
                              + (uint32_t)((lane >> 3) & 1) * 16;

    float c[16][4];
    #pragma unroll
    for (int t = 0; t < 16; t++)
        #pragma unroll
        for (int j = 0; j < 4; j++) c[t][j] = 0.0f;

    #pragma unroll
    for (int kk = 0; kk < 8; kk++) {                 // K = 8 * 16
        uint32_t a0, a1, a2, a3;
        LDSM4(a0, a1, a2, a3, aBase + kk * 32);
        #pragma unroll
        for (int bt = 0; bt < 8; bt++) {             // pairs of n8-tiles
            uint32_t b0, b1, b2, b3;
            LDSM4(b0, b1, b2, b3, bBase + (uint32_t)bt * 8 * RPITCH + kk * 32);
            MMA16816(c[2*bt],   a0, a1, a2, a3, b0, b1);
            MMA16816(c[2*bt+1], a0, a1, a2, a3, b2, b3);
        }
    }

    // ---- epilogue: max over the 16 rows of this warp's b-group ------------
    const int b = (m0 >> 4) + w;
    float* outRow = g_expc + (size_t)b * NCOLS + n0;

    #pragma unroll
    for (int t = 0; t < 16; t++) {
        float m0v = fmaxf(c[t][0], c[t][2]);         // rows lane/4 and +8
        float m1v = fmaxf(c[t][1], c[t][3]);
        #pragma unroll
        for (int o = 4; o <= 16; o <<= 1) {          // reduce over lane/4
            m0v = fmaxf(m0v, __shfl_xor_sync(0xffffffffu, m0v, o));
            m1v = fmaxf(m1v, __shfl_xor_sync(0xffffffffu, m1v, o));
        }
        if (lane < 4) {
            int col = n0 + t * 8 + lane * 2;
            if ((col >> 3) == b) {                   // this tile is b's diag
                g_diag[col]     = m0v;
                g_diag[col + 1] = m1v;
            }
            *(float2*)(outRow + t * 8 + lane * 2) =
                make_float2(__expf(m0v), __expf(m1v));
        }
    }
}

// ---------------------------------------------------------------------------
// 3a) Per-b row sum of exp + diag term.
// ---------------------------------------------------------------------------
__global__ void kred_i2t() {
    const int b = blockIdx.x, tid = threadIdx.x;
    const float4* row = (const float4*)(g_expc + (size_t)b * NCOLS);
    float s = 0.0f;
    #pragma unroll
    for (int j = tid; j < NCOLS / 4; j += 256) {
        float4 v = row[j];
        s += (v.x + v.y) + (v.z + v.w);
    }
    __shared__ float sm[256];
    sm[tid] = s; __syncthreads();
    for (int o = 128; o; o >>= 1) {
        if (tid < o) sm[tid] += sm[tid + o];
        __syncthreads();
    }
    if (tid == 0) {
        float d = 0.0f;
        #pragma unroll
        for (int t = 0; t < TT; t++) d += g_diag[b * TT + t];
        g_partial[b] = 1.125f * d - logf(sm[0]);       // (1 + 1/T) = 1.125
    }
}

// ---------------------------------------------------------------------------
// 3b) Column partial sums over 64 b's each (grid 16 x 8), no atomics.
// ---------------------------------------------------------------------------
__global__ void kred_t2i() {
    const int col = blockIdx.x * 256 + threadIdx.x;
    const int by  = blockIdx.y;
    const float* p = g_expc + (size_t)by * 64 * NCOLS + col;
    float s0 = 0, s1 = 0, s2 = 0, s3 = 0;
    #pragma unroll
    for (int bq = 0; bq < 16; bq++) {
        s0 += p[(size_t)(bq*4+0) * NCOLS];
        s1 += p[(size_t)(bq*4+1) * NCOLS];
        s2 += p[(size_t)(bq*4+2) * NCOLS];
        s3 += p[(size_t)(bq*4+3) * NCOLS];
    }
    g_t2ipart[by * NCOLS + col] = (s0 + s1) + (s2 + s3);
}

// ---------------------------------------------------------------------------
// 4) Final scalar.
// ---------------------------------------------------------------------------
__global__ void kfinal(float* __restrict__ out) {
    const int b = threadIdx.x;                  // 512 threads
    float v = g_partial[b];
    #pragma unroll
    for (int t = 0; t < TT; t++) {
        float den = 0.0f;
        #pragma unroll
        for (int s = 0; s < 8; s++) den += g_t2ipart[s * NCOLS + b * TT + t];
        v -= logf(den);
    }
    __shared__ float sm[512];
    sm[b] = v; __syncthreads();
    for (int o = 256; o; o >>= 1) {
        if (b < o) sm[b] += sm[b + o];
        __syncthreads();
    }
    if (b == 0) out[0] = -sm[0];
}

// ---------------------------------------------------------------------------
extern "C" void kernel_launch(void* const* d_in, const int* in_sizes, int n_in,
                              void* d_out, int out_size) {
    const float* img  = (const float*)d_in[0];
    const float* text = (const float*)d_in[1];
    if (n_in >= 2 && in_sizes[0] == NCOLS * DD && in_sizes[1] == MROWS * DD) {
        const float* t = img; img = text; text = t;
    }

    cudaFuncSetAttribute(kgemm, cudaFuncAttributeMaxDynamicSharedMemorySize, SM_BYTES);

    knorm<<<(MROWS + NCOLS) / 8, 256>>>(img, text);
    kgemm<<<dim3(NCOLS / 128, MROWS / 128), 256, SM_BYTES>>>();
    kred_i2t<<<BB, 256>>>();
    kred_t2i<<<dim3(16, 8), 256>>>();
    kfinal<<<1, 512>>>((float*)d_out);
}

// round 4
// speedup vs baseline: 5.1972x; 1.0946x over previous
#include <cuda_runtime.h>
#include <cuda_bf16.h>
#include <math.h>
#include <cstdint>

#define BB 512
#define ZI 16
#define TT 8
#define DD 128
#define MROWS (BB*ZI)   /* 8192 */
#define NCOLS (BB*TT)   /* 4096 */

// ---------------- scratch (static __device__, allocation-free) -------------
__device__ __nv_bfloat162 g_imgh [(size_t)MROWS * (DD/2)];   // 2 MB
__device__ __nv_bfloat162 g_texth[(size_t)NCOLS * (DD/2)];   // 1 MB
__device__ float g_diag[NCOLS];                              // raw covar diag
__device__ float g_rowpart[32 * BB];                         // per n-block row sums
__device__ float g_colpart[(size_t)64 * NCOLS];              // per m-block col sums
__device__ float g_dent2i[NCOLS];

__device__ __forceinline__ uint32_t smem_u32(const void* p) {
    uint32_t a;
    asm("{ .reg .u64 t; cvta.to.shared.u64 t, %1; cvt.u32.u64 %0, t; }"
        : "=r"(a) : "l"(p));
    return a;
}

#define LDSM4(r0,r1,r2,r3,addr) \
    asm volatile("ldmatrix.sync.aligned.m8n8.x4.shared.b16 {%0,%1,%2,%3}, [%4];" \
                 : "=r"(r0),"=r"(r1),"=r"(r2),"=r"(r3) : "r"(addr))

#define MMA16816(c,a0,a1,a2,a3,b0,b1) \
    asm volatile("mma.sync.aligned.m16n8k16.row.col.f32.bf16.bf16.f32 " \
                 "{%0,%1,%2,%3},{%4,%5,%6,%7},{%8,%9},{%0,%1,%2,%3};" \
                 : "+f"(c[0]),"+f"(c[1]),"+f"(c[2]),"+f"(c[3]) \
                 : "r"(a0),"r"(a1),"r"(a2),"r"(a3),"r"(b0),"r"(b1))

// ---------------------------------------------------------------------------
// 1) L2 normalize + convert to packed bf16. One warp per row of 128 floats.
// ---------------------------------------------------------------------------
__global__ void knorm(const float* __restrict__ img, const float* __restrict__ text) {
    int wid  = blockIdx.x * 8 + (threadIdx.x >> 5);
    int lane = threadIdx.x & 31;
    const float* src; __nv_bfloat162* dst;
    if (wid < MROWS) { src = img + (size_t)wid * DD;  dst = g_imgh + (size_t)wid * (DD/2); }
    else { int r = wid - MROWS; src = text + (size_t)r * DD; dst = g_texth + (size_t)r * (DD/2); }
    float4 v = ((const float4*)src)[lane];
    float s = v.x*v.x + v.y*v.y + v.z*v.z + v.w*v.w;
    #pragma unroll
    for (int o = 16; o; o >>= 1) s += __shfl_xor_sync(0xffffffffu, s, o);
    float inv = 1.0f / fmaxf(sqrtf(s), 1e-12f);
    dst[lane*2]   = __floats2bfloat162_rn(v.x*inv, v.y*inv);
    dst[lane*2+1] = __floats2bfloat162_rn(v.z*inv, v.w*inv);
}

// ---------------------------------------------------------------------------
// 2) HMMA bf16 GEMM + max-over-i + exp + FUSED partial reductions.
//    CTA tile 128x128x128, 256 threads. Warp w owns m-rows [16w,16w+16)
//    = one b-group, all 128 n-cols. Epilogue emits:
//      g_rowpart[n_blk][b]      (sum of exp over this CTA's 128 cols)
//      g_colpart[m_blk][col]    (sum of exp over this CTA's 8 b's)
//      g_diag[col]              (raw covar on the b==col/8 diagonal)
//    No full covar/exp matrix ever touches DRAM.
// ---------------------------------------------------------------------------
#define RPITCH 272
#define SM_BYTES (2 * 128 * RPITCH)     /* 69632 dynamic */

__global__ void __launch_bounds__(256) kgemm() {
    extern __shared__ char sh[];
    char* shA = sh;
    char* shB = sh + 128 * RPITCH;
    __shared__ float scol[8 * 128];     // static: per-warp exp rows

    const int tid  = threadIdx.x;
    const int lane = tid & 31, w = tid >> 5;
    const int m0 = blockIdx.y * 128, n0 = blockIdx.x * 128;

    // ---- load tiles (each row: 128 bf16 = 16 uint4), pad rows to 272B -----
    const uint4* gA = (const uint4*)(g_imgh  + (size_t)m0 * (DD/2));
    const uint4* gB = (const uint4*)(g_texth + (size_t)n0 * (DD/2));
    #pragma unroll
    for (int it = tid; it < 2048; it += 256) {
        int row = it >> 4, q = it & 15;
        *(uint4*)(shA + row * RPITCH + q * 16) = gA[it];
        *(uint4*)(shB + row * RPITCH + q * 16) = gB[it];
    }
    __syncthreads();

    const uint32_t sA = smem_u32(shA), sB = smem_u32(shB);
    const uint32_t aBase = sA + (uint32_t)(w * 16 + (lane & 15)) * RPITCH
                              + (uint32_t)(lane >> 4) * 16;
    const uint32_t bBase = sB + (uint32_t)((lane & 7) + ((lane >> 4) << 3)) * RPITCH
                              + (uint32_t)((lane >> 3) & 1) * 16;

    float c[16][4];
    #pragma unroll
    for (int t = 0; t < 16; t++)
        #pragma unroll
        for (int j = 0; j < 4; j++) c[t][j] = 0.0f;

    #pragma unroll
    for (int kk = 0; kk < 8; kk++) {                 // K = 8 * 16
        uint32_t a0, a1, a2, a3;
        LDSM4(a0, a1, a2, a3, aBase + kk * 32);
        #pragma unroll
        for (int bt = 0; bt < 8; bt++) {
            uint32_t b0, b1, b2, b3;
            LDSM4(b0, b1, b2, b3, bBase + (uint32_t)bt * 8 * RPITCH + kk * 32);
            MMA16816(c[2*bt],   a0, a1, a2, a3, b0, b1);
            MMA16816(c[2*bt+1], a0, a1, a2, a3, b2, b3);
        }
    }

    // ---- epilogue ---------------------------------------------------------
    const int b = (m0 >> 4) + w;
    float* scolw = scol + w * 128;
    float rowsum = 0.0f;

    #pragma unroll
    for (int t = 0; t < 16; t++) {
        float m0v = fmaxf(c[t][0], c[t][2]);
        float m1v = fmaxf(c[t][1], c[t][3]);
        #pragma unroll
        for (int o = 4; o <= 16; o <<= 1) {
            m0v = fmaxf(m0v, __shfl_xor_sync(0xffffffffu, m0v, o));
            m1v = fmaxf(m1v, __shfl_xor_sync(0xffffffffu, m1v, o));
        }
        if (lane < 4) {
            int colL = t * 8 + lane * 2;
            int col  = n0 + colL;
            if ((col >> 3) == b) {                   // diagonal tile of b
                g_diag[col]     = m0v;
                g_diag[col + 1] = m1v;
            }
            float e0 = __expf(m0v), e1 = __expf(m1v);
            scolw[colL]     = e0;
            scolw[colL + 1] = e1;
            rowsum += e0 + e1;
        }
    }

    // row partial: reduce lanes 0..3 (others hold 0)
    rowsum += __shfl_xor_sync(0xffffffffu, rowsum, 1);
    rowsum += __shfl_xor_sync(0xffffffffu, rowsum, 2);
    if (lane == 0) g_rowpart[blockIdx.x * BB + b] = rowsum;

    // col partials: deterministic tree over the 8 warps
    __syncthreads();
    if (tid < 128) {
        float s = 0.0f;
        #pragma unroll
        for (int ww = 0; ww < 8; ww++) s += scol[ww * 128 + tid];
        g_colpart[(size_t)blockIdx.y * NCOLS + n0 + tid] = s;
    }
}

// ---------------------------------------------------------------------------
// 3) den_t2i[col] = sum over 64 m-blocks of col partials. 1 MB read.
// ---------------------------------------------------------------------------
__global__ void kredcol() {
    const int col = blockIdx.x * 256 + threadIdx.x;
    float s = 0.0f;
    #pragma unroll
    for (int j = 0; j < 64; j++) s += g_colpart[(size_t)j * NCOLS + col];
    g_dent2i[col] = s;
}

// ---------------------------------------------------------------------------
// 4) Final scalar.
// ---------------------------------------------------------------------------
__global__ void kfinal(float* __restrict__ out) {
    const int b = threadIdx.x;                  // 512 threads
    float den = 0.0f;
    #pragma unroll
    for (int j = 0; j < 32; j++) den += g_rowpart[j * BB + b];
    float d = 0.0f;
    #pragma unroll
    for (int t = 0; t < TT; t++) d += g_diag[b * TT + t];
    float v = 1.125f * d - logf(den);           // (1 + 1/T) = 1.125
    #pragma unroll
    for (int t = 0; t < TT; t++) v -= logf(g_dent2i[b * TT + t]);

    __shared__ float sm[512];
    sm[b] = v; __syncthreads();
    for (int o = 256; o; o >>= 1) {
        if (b < o) sm[b] += sm[b + o];
        __syncthreads();
    }
    if (b == 0) out[0] = -sm[0];
}

// ---------------------------------------------------------------------------
extern "C" void kernel_launch(void* const* d_in, const int* in_sizes, int n_in,
                              void* d_out, int out_size) {
    const float* img  = (const float*)d_in[0];
    const float* text = (const float*)d_in[1];
    if (n_in >= 2 && in_sizes[0] == NCOLS * DD && in_sizes[1] == MROWS * DD) {
        const float* t = img; img = text; text = t;
    }

    cudaFuncSetAttribute(kgemm, cudaFuncAttributeMaxDynamicSharedMemorySize, SM_BYTES);

    knorm<<<(MROWS + NCOLS) / 8, 256>>>(img, text);
    kgemm<<<dim3(NCOLS / 128, MROWS / 128), 256, SM_BYTES>>>();
    kredcol<<<NCOLS / 256, 256>>>();
    kfinal<<<1, 512>>>((float*)d_out);
}

// round 5
// speedup vs baseline: 5.5012x; 1.0585x over previous
#include <cuda_runtime.h>
#include <cuda_bf16.h>
#include <math.h>
#include <cstdint>

#define BB 512
#define ZI 16
#define TT 8
#define DD 128
#define MROWS (BB*ZI)   /* 8192 */
#define NCOLS (BB*TT)   /* 4096 */

// ---------------- scratch (static __device__, allocation-free) -------------
__device__ __nv_bfloat162 g_imgh [(size_t)MROWS * (DD/2)];   // 2 MB
__device__ __nv_bfloat162 g_texth[(size_t)NCOLS * (DD/2)];   // 1 MB
__device__ float g_diag[NCOLS];                              // raw covar diag
__device__ float g_rowpart[32 * BB];                         // per n-block row sums
__device__ float g_colpart[(size_t)64 * NCOLS];              // per m-block col sums
__device__ float g_logden[NCOLS];                            // log den_t2i
__device__ float g_logrow[BB];                               // log den_i2t

__device__ __forceinline__ uint32_t smem_u32(const void* p) {
    uint32_t a;
    asm("{ .reg .u64 t; cvta.to.shared.u64 t, %1; cvt.u32.u64 %0, t; }"
        : "=r"(a) : "l"(p));
    return a;
}

#define CPASYNC16(dst,src) \
    asm volatile("cp.async.ca.shared.global [%0], [%1], 16;" \
                 :: "r"(dst), "l"(src) : "memory")

#define LDSM4(r0,r1,r2,r3,addr) \
    asm volatile("ldmatrix.sync.aligned.m8n8.x4.shared.b16 {%0,%1,%2,%3}, [%4];" \
                 : "=r"(r0),"=r"(r1),"=r"(r2),"=r"(r3) : "r"(addr))

#define MMA16816(c,a0,a1,a2,a3,b0,b1) \
    asm volatile("mma.sync.aligned.m16n8k16.row.col.f32.bf16.bf16.f32 " \
                 "{%0,%1,%2,%3},{%4,%5,%6,%7},{%8,%9},{%0,%1,%2,%3};" \
                 : "+f"(c[0]),"+f"(c[1]),"+f"(c[2]),"+f"(c[3]) \
                 : "r"(a0),"r"(a1),"r"(a2),"r"(a3),"r"(b0),"r"(b1))

// ---------------------------------------------------------------------------
// 1) L2 normalize + convert to packed bf16. One warp per row of 128 floats.
// ---------------------------------------------------------------------------
__global__ void knorm(const float* __restrict__ img, const float* __restrict__ text) {
    int wid  = blockIdx.x * 8 + (threadIdx.x >> 5);
    int lane = threadIdx.x & 31;
    const float* src; __nv_bfloat162* dst;
    if (wid < MROWS) { src = img + (size_t)wid * DD;  dst = g_imgh + (size_t)wid * (DD/2); }
    else { int r = wid - MROWS; src = text + (size_t)r * DD; dst = g_texth + (size_t)r * (DD/2); }
    float4 v = ((const float4*)src)[lane];
    float s = v.x*v.x + v.y*v.y + v.z*v.z + v.w*v.w;
    #pragma unroll
    for (int o = 16; o; o >>= 1) s += __shfl_xor_sync(0xffffffffu, s, o);
    float inv = 1.0f / fmaxf(sqrtf(s), 1e-12f);
    dst[lane*2]   = __floats2bfloat162_rn(v.x*inv, v.y*inv);
    dst[lane*2+1] = __floats2bfloat162_rn(v.z*inv, v.w*inv);
}

// ---------------------------------------------------------------------------
// 2) HMMA bf16 GEMM + max-over-i + exp + fused partial reductions.
//    CTA tile 128x128x128, 256 threads; cp.async tile loads.
// ---------------------------------------------------------------------------
#define RPITCH 272
#define SM_BYTES (2 * 128 * RPITCH)     /* 69632 dynamic */

__global__ void __launch_bounds__(256) kgemm() {
    extern __shared__ char sh[];
    char* shA = sh;
    char* shB = sh + 128 * RPITCH;
    __shared__ float scol[8 * 128];

    const int tid  = threadIdx.x;
    const int lane = tid & 31, w = tid >> 5;
    const int m0 = blockIdx.y * 128, n0 = blockIdx.x * 128;

    // ---- async tile loads: 128 rows x 256B each, rows padded to 272B ------
    const uint32_t sA = smem_u32(shA), sB = smem_u32(shB);
    const uint4* gA = (const uint4*)(g_imgh  + (size_t)m0 * (DD/2));
    const uint4* gB = (const uint4*)(g_texth + (size_t)n0 * (DD/2));
    #pragma unroll
    for (int it = tid; it < 2048; it += 256) {
        int row = it >> 4, q = it & 15;
        uint32_t so = row * RPITCH + q * 16;
        CPASYNC16(sA + so, gA + it);
        CPASYNC16(sB + so, gB + it);
    }
    asm volatile("cp.async.commit_group;" ::: "memory");
    asm volatile("cp.async.wait_group 0;" ::: "memory");
    __syncthreads();

    const uint32_t aBase = sA + (uint32_t)(w * 16 + (lane & 15)) * RPITCH
                              + (uint32_t)(lane >> 4) * 16;
    const uint32_t bBase = sB + (uint32_t)((lane & 7) + ((lane >> 4) << 3)) * RPITCH
                              + (uint32_t)((lane >> 3) & 1) * 16;

    float c[16][4];
    #pragma unroll
    for (int t = 0; t < 16; t++)
        #pragma unroll
        for (int j = 0; j < 4; j++) c[t][j] = 0.0f;

    #pragma unroll
    for (int kk = 0; kk < 8; kk++) {                 // K = 8 * 16
        uint32_t a0, a1, a2, a3;
        LDSM4(a0, a1, a2, a3, aBase + kk * 32);
        #pragma unroll
        for (int bt = 0; bt < 8; bt++) {
            uint32_t b0, b1, b2, b3;
            LDSM4(b0, b1, b2, b3, bBase + (uint32_t)bt * 8 * RPITCH + kk * 32);
            MMA16816(c[2*bt],   a0, a1, a2, a3, b0, b1);
            MMA16816(c[2*bt+1], a0, a1, a2, a3, b2, b3);
        }
    }

    // ---- epilogue: max over the 16 rows of this warp's b-group ------------
    const int b = (m0 >> 4) + w;
    float* scolw = scol + w * 128;
    float rowsum = 0.0f;

    #pragma unroll
    for (int t = 0; t < 16; t++) {
        float m0v = fmaxf(c[t][0], c[t][2]);
        float m1v = fmaxf(c[t][1], c[t][3]);
        #pragma unroll
        for (int o = 4; o <= 16; o <<= 1) {
            m0v = fmaxf(m0v, __shfl_xor_sync(0xffffffffu, m0v, o));
            m1v = fmaxf(m1v, __shfl_xor_sync(0xffffffffu, m1v, o));
        }
        if (lane < 4) {
            int colL = t * 8 + lane * 2;
            int col  = n0 + colL;
            if ((col >> 3) == b) {                   // diagonal tile of b
                g_diag[col]     = m0v;
                g_diag[col + 1] = m1v;
            }
            float e0 = __expf(m0v), e1 = __expf(m1v);
            scolw[colL]     = e0;
            scolw[colL + 1] = e1;
            rowsum += e0 + e1;
        }
    }

    rowsum += __shfl_xor_sync(0xffffffffu, rowsum, 1);
    rowsum += __shfl_xor_sync(0xffffffffu, rowsum, 2);
    if (lane == 0) g_rowpart[blockIdx.x * BB + b] = rowsum;

    __syncthreads();
    if (tid < 128) {
        float s = 0.0f;
        #pragma unroll
        for (int ww = 0; ww < 8; ww++) s += scol[ww * 128 + tid];
        g_colpart[(size_t)blockIdx.y * NCOLS + n0 + tid] = s;
    }
}

// ---------------------------------------------------------------------------
// 3) Parallel log-reductions:
//    blocks 0..15 : logden[col] = log( sum_m colpart )   (256 cols/block)
//    blocks 16,17 : logrow[b]   = log( sum_n rowpart )    (256 b's/block)
// ---------------------------------------------------------------------------
__global__ void kred() {
    if (blockIdx.x < 16) {
        const int col = blockIdx.x * 256 + threadIdx.x;
        float s = 0.0f;
        #pragma unroll
        for (int j = 0; j < 64; j++) s += g_colpart[(size_t)j * NCOLS + col];
        g_logden[col] = logf(s);
    } else {
        const int b = (blockIdx.x - 16) * 256 + threadIdx.x;
        float s = 0.0f;
        #pragma unroll
        for (int j = 0; j < 32; j++) s += g_rowpart[j * BB + b];
        g_logrow[b] = logf(s);
    }
}

// ---------------------------------------------------------------------------
// 4) Final scalar — everything precomputed, just gather + add-tree.
// ---------------------------------------------------------------------------
__global__ void kfinal(float* __restrict__ out) {
    const int b = threadIdx.x;                  // 512 threads
    float d = 0.0f, l = 0.0f;
    #pragma unroll
    for (int t = 0; t < TT; t++) {
        d += g_diag[b * TT + t];
        l += g_logden[b * TT + t];
    }
    float v = 1.125f * d - g_logrow[b] - l;     // (1 + 1/T) = 1.125

    __shared__ float sm[512];
    sm[b] = v; __syncthreads();
    for (int o = 256; o; o >>= 1) {
        if (b < o) sm[b] += sm[b + o];
        __syncthreads();
    }
    if (b == 0) out[0] = -sm[0];
}

// ---------------------------------------------------------------------------
extern "C" void kernel_launch(void* const* d_in, const int* in_sizes, int n_in,
                              void* d_out, int out_size) {
    const float* img  = (const float*)d_in[0];
    const float* text = (const float*)d_in[1];
    if (n_in >= 2 && in_sizes[0] == NCOLS * DD && in_sizes[1] == MROWS * DD) {
        const float* t = img; img = text; text = t;
    }

    cudaFuncSetAttribute(kgemm, cudaFuncAttributeMaxDynamicSharedMemorySize, SM_BYTES);

    knorm<<<(MROWS + NCOLS) / 8, 256>>>(img, text);
    kgemm<<<dim3(NCOLS / 128, MROWS / 128), 256, SM_BYTES>>>();
    kred<<<18, 256>>>();
    kfinal<<<1, 512>>>((float*)d_out);
}